// round 12
// baseline (speedup 1.0000x reference)
#include <cuda_runtime.h>
#include <float.h>

// features [4,256,50,50] f32, rois [128,5] f32 (b,x1,y1,x2,y2),
// out [128,256,7,7] f32. Caffe geometry + reciprocal-multiply bin size
// (bin = roi * fl32(1/7)) — bit-exact vs gold (round 9).
//
// ROUND 12: load-balance fix. Thread index order (bin, n, c) so each block
// mixes ~5 different ROIs (window work varies 25x across ROIs; the old
// (bin, c, n) order gave every block/wave a single ROI's workload and the
// big-ROI block clusters set the critical path).

#define NBINS  49
#define NROI   128
#define NCH    256
#define OUT_ELEMS 1605632          // 128*256*49
#define PLANE  2500

__device__ unsigned int g_edges[NROI * NBINS];  // w0|w1<<8|h0<<16|h1<<24
__device__ int          g_batch[NROI];

__global__ void edges_kernel(const float* __restrict__ rois)
{
    const int idx = blockIdx.x * blockDim.x + threadIdx.x;
    if (idx >= NROI * NBINS) return;

    const int bin = idx % NBINS;
    const int n   = idx / NBINS;
    const int pw  = bin % 7;
    const int ph  = bin / 7;

    const float* r = rois + n * 5;
    const float x1 = rintf(r[1] * 0.0625f);   // exact *2^-4, half-even
    const float y1 = rintf(r[2] * 0.0625f);
    const float x2 = rintf(r[3] * 0.0625f);
    const float y2 = rintf(r[4] * 0.0625f);

    const float roi_w = fmaxf(x2 - x1 + 1.0f, 1.0f);
    const float roi_h = fmaxf(y2 - y1 + 1.0f, 1.0f);

    const float C7 = 1.0f / 7.0f;             // fl32(1/7)
    const float bw = __fmul_rn(roi_w, C7);    // reciprocal-multiply div
    const float bh = __fmul_rn(roi_h, C7);

    const float wstart = fminf(fmaxf(floorf(__fmul_rn((float)pw, bw))        + x1, 0.0f), 50.0f);
    const float wend   = fminf(fmaxf(ceilf (__fmul_rn((float)pw + 1.0f, bw)) + x1, 0.0f), 50.0f);
    const float hstart = fminf(fmaxf(floorf(__fmul_rn((float)ph, bh))        + y1, 0.0f), 50.0f);
    const float hend   = fminf(fmaxf(ceilf (__fmul_rn((float)ph + 1.0f, bh)) + y1, 0.0f), 50.0f);

    const unsigned int w0 = (unsigned int)(int)wstart;
    const unsigned int w1 = (unsigned int)(int)wend;
    const unsigned int h0 = (unsigned int)(int)hstart;
    const unsigned int h1 = (unsigned int)(int)hend;

    g_edges[idx] = w0 | (w1 << 8) | (h0 << 16) | (h1 << 24);
    if (bin == 0) g_batch[n] = (int)r[0];
}

__global__ void pool_kernel(const float* __restrict__ feat,
                            float* __restrict__ out)
{
    const int idx = blockIdx.x * blockDim.x + threadIdx.x;
    if (idx >= OUT_ELEMS) return;

    // BALANCED ORDER: bin fastest, then n (ROI), then c.
    const int bin = idx % NBINS;
    const int n   = (idx / NBINS) & 127;          // NROI = 128
    const int c   = idx / (NBINS * NROI);

    const unsigned int e = g_edges[n * NBINS + bin];  // L1-hot
    const int w0 = (int)(e & 0xFF);
    const int w1 = (int)((e >> 8) & 0xFF);
    const int h0 = (int)((e >> 16) & 0xFF);
    const int h1 = (int)(e >> 24);
    const int b  = g_batch[n];

    const float* __restrict__ plane = feat + ((size_t)b * NCH + c) * PLANE;

    float m = -FLT_MAX;
    for (int h = h0; h < h1; ++h) {
        const float* rowp = plane + h * 50;
        for (int w = w0; w < w1; ++w) {
            m = fmaxf(m, __ldg(rowp + w));
        }
    }

    // out is [n, c, bin]
    out[(n * NCH + c) * NBINS + bin] = (w1 > w0 && h1 > h0) ? m : 0.0f;
}

extern "C" void kernel_launch(void* const* d_in, const int* in_sizes, int n_in,
                              void* d_out, int out_size)
{
    const float* feat = nullptr;
    const float* rois = nullptr;
    for (int i = 0; i < n_in; ++i) {
        long s = in_sizes[i];
        if (s == 2560000L || s == 10240000L) feat = (const float*)d_in[i];
        else if (s == 640L || s == 2560L)    rois = (const float*)d_in[i];
    }
    if (!feat) feat = (const float*)d_in[0];
    if (!rois) rois = (const float*)d_in[n_in > 1 ? 1 : 0];

    edges_kernel<<<(NROI * NBINS + 255) / 256, 256>>>(rois);   // 25 blocks
    pool_kernel<<<(OUT_ELEMS + 255) / 256, 256>>>(feat, (float*)d_out);
}

// round 13
// speedup vs baseline: 1.1706x; 1.1706x over previous
#include <cuda_runtime.h>
#include <float.h>

// features [4,256,50,50] f32, rois [128,5] f32, out [128,256,7,7] f32.
// Caffe geometry + reciprocal-multiply bin (roi * fl32(1/7)) — bit-exact gold.
//
// ROUND 13: NCHW -> NHWC transpose into scratch, then c-vectorized pooling:
// thread = (n, bin, c4), warp = 128 consecutive channels of ONE bin ->
// zero divergence, fully coalesced 512B window-cell loads, 4 outputs/thread.

#define NBINS 49
#define NROI  128
#define NCH   256
#define PLANE 2500                      // 50*50
#define POOL_THREADS (NROI * NBINS * 64)  // 401,408

__device__ __align__(16) float g_tfeat[4 * PLANE * NCH];  // NHWC scratch, 10.24 MB
__device__ unsigned int g_edges[NROI * NBINS];            // w0|w1<<8|h0<<16|h1<<24
__device__ int          g_batch[NROI];

__global__ void edges_kernel(const float* __restrict__ rois)
{
    const int idx = blockIdx.x * blockDim.x + threadIdx.x;
    if (idx >= NROI * NBINS) return;

    const int bin = idx % NBINS;
    const int n   = idx / NBINS;
    const int pw  = bin % 7;
    const int ph  = bin / 7;

    const float* r = rois + n * 5;
    const float x1 = rintf(r[1] * 0.0625f);
    const float y1 = rintf(r[2] * 0.0625f);
    const float x2 = rintf(r[3] * 0.0625f);
    const float y2 = rintf(r[4] * 0.0625f);

    const float roi_w = fmaxf(x2 - x1 + 1.0f, 1.0f);
    const float roi_h = fmaxf(y2 - y1 + 1.0f, 1.0f);

    const float C7 = 1.0f / 7.0f;              // fl32(1/7)
    const float bw = __fmul_rn(roi_w, C7);     // reciprocal-multiply div
    const float bh = __fmul_rn(roi_h, C7);

    const float wstart = fminf(fmaxf(floorf(__fmul_rn((float)pw, bw))        + x1, 0.0f), 50.0f);
    const float wend   = fminf(fmaxf(ceilf (__fmul_rn((float)pw + 1.0f, bw)) + x1, 0.0f), 50.0f);
    const float hstart = fminf(fmaxf(floorf(__fmul_rn((float)ph, bh))        + y1, 0.0f), 50.0f);
    const float hend   = fminf(fmaxf(ceilf (__fmul_rn((float)ph + 1.0f, bh)) + y1, 0.0f), 50.0f);

    const unsigned int w0 = (unsigned int)(int)wstart;
    const unsigned int w1 = (unsigned int)(int)wend;
    const unsigned int h0 = (unsigned int)(int)hstart;
    const unsigned int h1 = (unsigned int)(int)hend;

    g_edges[idx] = w0 | (w1 << 8) | (h0 << 16) | (h1 << 24);
    if (bin == 0) g_batch[n] = (int)r[0];
}

// NCHW -> NHWC: g_tfeat[(b*2500 + hw)*256 + c] = feat[(b*256 + c)*2500 + hw]
__global__ void transpose_kernel(const float* __restrict__ feat)
{
    __shared__ float tile[32][33];
    const int b   = blockIdx.z;
    const int c0  = blockIdx.y * 32;
    const int hw0 = blockIdx.x * 32;
    const int tx  = threadIdx.x;      // 0..31
    const int ty  = threadIdx.y;      // 0..7

#pragma unroll
    for (int i = 0; i < 4; ++i) {
        const int c  = c0 + ty + i * 8;
        const int hw = hw0 + tx;
        if (hw < PLANE)
            tile[ty + i * 8][tx] = feat[((size_t)b * NCH + c) * PLANE + hw];
    }
    __syncthreads();
#pragma unroll
    for (int i = 0; i < 4; ++i) {
        const int hw = hw0 + ty + i * 8;
        const int c  = c0 + tx;
        if (hw < PLANE)
            g_tfeat[((size_t)b * PLANE + hw) * NCH + c] = tile[tx][ty + i * 8];
    }
}

__global__ void pool_kernel(float* __restrict__ out)
{
    const int idx = blockIdx.x * blockDim.x + threadIdx.x;
    if (idx >= POOL_THREADS) return;

    const int c4  = idx & 63;        // fastest -> warp = 128 channels of one bin
    const int t   = idx >> 6;
    const int bin = t % NBINS;
    const int n   = t / NBINS;

    const unsigned int e = g_edges[n * NBINS + bin];   // uniform per warp
    const int w0 = (int)(e & 0xFF);
    const int w1 = (int)((e >> 8) & 0xFF);
    const int h0 = (int)((e >> 16) & 0xFF);
    const int h1 = (int)(e >> 24);
    const int b  = g_batch[n];

    const float* __restrict__ base = g_tfeat + (size_t)b * PLANE * NCH + c4 * 4;

    float4 m = make_float4(-FLT_MAX, -FLT_MAX, -FLT_MAX, -FLT_MAX);
    for (int h = h0; h < h1; ++h) {
        const float* rp = base + (h * 50) * NCH;
        for (int w = w0; w < w1; ++w) {
            const float4 v = *reinterpret_cast<const float4*>(rp + w * NCH);
            m.x = fmaxf(m.x, v.x);
            m.y = fmaxf(m.y, v.y);
            m.z = fmaxf(m.z, v.z);
            m.w = fmaxf(m.w, v.w);
        }
    }

    const bool ne = (w1 > w0) && (h1 > h0);
    const int ob = (n * NCH + c4 * 4) * NBINS + bin;   // out [n, c, bin]
    out[ob]             = ne ? m.x : 0.0f;
    out[ob + NBINS]     = ne ? m.y : 0.0f;
    out[ob + 2 * NBINS] = ne ? m.z : 0.0f;
    out[ob + 3 * NBINS] = ne ? m.w : 0.0f;
}

extern "C" void kernel_launch(void* const* d_in, const int* in_sizes, int n_in,
                              void* d_out, int out_size)
{
    const float* feat = nullptr;
    const float* rois = nullptr;
    for (int i = 0; i < n_in; ++i) {
        long s = in_sizes[i];
        if (s == 2560000L || s == 10240000L) feat = (const float*)d_in[i];
        else if (s == 640L || s == 2560L)    rois = (const float*)d_in[i];
    }
    if (!feat) feat = (const float*)d_in[0];
    if (!rois) rois = (const float*)d_in[n_in > 1 ? 1 : 0];

    edges_kernel<<<(NROI * NBINS + 255) / 256, 256>>>(rois);

    dim3 tb(32, 8);
    dim3 tg((PLANE + 31) / 32, NCH / 32, 4);   // 79 x 8 x 4
    transpose_kernel<<<tg, tb>>>(feat);

    pool_kernel<<<(POOL_THREADS + 255) / 256, 256>>>((float*)d_out);
}

// round 14
// speedup vs baseline: 1.2530x; 1.0704x over previous
#include <cuda_runtime.h>
#include <float.h>

// features [4,256,50,50] f32, rois [128,5] f32, out [128,256,7,7] f32.
// Caffe geometry + reciprocal-multiply bin (roi * fl32(1/7)) — bit-exact gold.
//
// ROUND 14: two launches only.
//   K1: NCHW -> NHWC transpose into __device__ scratch.
//   K2: c-vectorized pool; bin edges computed INLINE (warp-uniform, since a
//       warp covers 128 consecutive channels of one (n,bin)). No edge table,
//       no third launch (round 13 lost 4.2us to the serialized tiny kernel).

#define NBINS 49
#define NROI  128
#define NCH   256
#define PLANE 2500                        // 50*50
#define POOL_THREADS (NROI * NBINS * 64)  // 401,408

__device__ __align__(16) float g_tfeat[4 * PLANE * NCH];  // NHWC, 10.24 MB

// NCHW -> NHWC: g_tfeat[(b*2500 + hw)*256 + c] = feat[(b*256 + c)*2500 + hw]
__global__ void transpose_kernel(const float* __restrict__ feat)
{
    __shared__ float tile[32][33];
    const int b   = blockIdx.z;
    const int c0  = blockIdx.y * 32;
    const int hw0 = blockIdx.x * 32;
    const int tx  = threadIdx.x;      // 0..31
    const int ty  = threadIdx.y;      // 0..7

#pragma unroll
    for (int i = 0; i < 4; ++i) {
        const int c  = c0 + ty + i * 8;
        const int hw = hw0 + tx;
        if (hw < PLANE)
            tile[ty + i * 8][tx] = feat[((size_t)b * NCH + c) * PLANE + hw];
    }
    __syncthreads();
#pragma unroll
    for (int i = 0; i < 4; ++i) {
        const int hw = hw0 + ty + i * 8;
        const int c  = c0 + tx;
        if (hw < PLANE)
            g_tfeat[((size_t)b * PLANE + hw) * NCH + c] = tile[tx][ty + i * 8];
    }
}

__global__ void pool_kernel(const float* __restrict__ rois,
                            float* __restrict__ out)
{
    const int idx = blockIdx.x * blockDim.x + threadIdx.x;
    if (idx >= POOL_THREADS) return;

    const int c4  = idx & 63;        // fastest -> warp = 128 channels of one bin
    const int t   = idx >> 6;
    const int bin = t % NBINS;
    const int n   = t / NBINS;
    const int pw  = bin % 7;
    const int ph  = bin / 7;

    // ---- inline edge math (warp-uniform; bit-exact round-9 semantics) ----
    const float* r = rois + n * 5;
    const int   b  = (int)r[0];
    const float x1 = rintf(r[1] * 0.0625f);
    const float y1 = rintf(r[2] * 0.0625f);
    const float x2 = rintf(r[3] * 0.0625f);
    const float y2 = rintf(r[4] * 0.0625f);

    const float roi_w = fmaxf(x2 - x1 + 1.0f, 1.0f);
    const float roi_h = fmaxf(y2 - y1 + 1.0f, 1.0f);

    const float C7 = 1.0f / 7.0f;              // fl32(1/7)
    const float bw = __fmul_rn(roi_w, C7);     // reciprocal-multiply div
    const float bh = __fmul_rn(roi_h, C7);

    const float wstart = fminf(fmaxf(floorf(__fmul_rn((float)pw, bw))        + x1, 0.0f), 50.0f);
    const float wend   = fminf(fmaxf(ceilf (__fmul_rn((float)pw + 1.0f, bw)) + x1, 0.0f), 50.0f);
    const float hstart = fminf(fmaxf(floorf(__fmul_rn((float)ph, bh))        + y1, 0.0f), 50.0f);
    const float hend   = fminf(fmaxf(ceilf (__fmul_rn((float)ph + 1.0f, bh)) + y1, 0.0f), 50.0f);

    const int w0 = (int)wstart, w1 = (int)wend;
    const int h0 = (int)hstart, h1 = (int)hend;

    // ---- c-vectorized window scan (coalesced 512B per warp per cell) ----
    const float* __restrict__ base = g_tfeat + (size_t)b * PLANE * NCH + c4 * 4;

    float4 m = make_float4(-FLT_MAX, -FLT_MAX, -FLT_MAX, -FLT_MAX);
    for (int h = h0; h < h1; ++h) {
        const float* rp = base + (h * 50) * NCH;
        for (int w = w0; w < w1; ++w) {
            const float4 v = *reinterpret_cast<const float4*>(rp + w * NCH);
            m.x = fmaxf(m.x, v.x);
            m.y = fmaxf(m.y, v.y);
            m.z = fmaxf(m.z, v.z);
            m.w = fmaxf(m.w, v.w);
        }
    }

    const bool ne = (w1 > w0) && (h1 > h0);
    const int ob = (n * NCH + c4 * 4) * NBINS + bin;   // out [n, c, bin]
    out[ob]             = ne ? m.x : 0.0f;
    out[ob + NBINS]     = ne ? m.y : 0.0f;
    out[ob + 2 * NBINS] = ne ? m.z : 0.0f;
    out[ob + 3 * NBINS] = ne ? m.w : 0.0f;
}

extern "C" void kernel_launch(void* const* d_in, const int* in_sizes, int n_in,
                              void* d_out, int out_size)
{
    const float* feat = nullptr;
    const float* rois = nullptr;
    for (int i = 0; i < n_in; ++i) {
        long s = in_sizes[i];
        if (s == 2560000L || s == 10240000L) feat = (const float*)d_in[i];
        else if (s == 640L || s == 2560L)    rois = (const float*)d_in[i];
    }
    if (!feat) feat = (const float*)d_in[0];
    if (!rois) rois = (const float*)d_in[n_in > 1 ? 1 : 0];

    dim3 tb(32, 8);
    dim3 tg((PLANE + 31) / 32, NCH / 32, 4);   // 79 x 8 x 4 = 2528 blocks
    transpose_kernel<<<tg, tb>>>(feat);

    pool_kernel<<<(POOL_THREADS + 255) / 256, 256>>>(rois, (float*)d_out);
}